// round 11
// baseline (speedup 1.0000x reference)
#include <cuda_runtime.h>
#include <math.h>

// Problem constants
#define T_TOK 8192
#define DDIM  4096
#define NEXP  64
#define TOPK  8

// GEMM tiling
#define BM    64
#define BK    16
#define NTH   256
#define KHALF (DDIM / 2)       // 2048 (split-K = 2, contiguous halves)
#define NITER (KHALF / BK)     // 128
#define WDUP  128              // duplicated-W row: 64 experts x 2

// Packed fp32x2 FMA: two independent IEEE-rn fp32 FMAs (bit-exact vs 2x fmaf)
#define FMA2(c, a, b) \
    asm("fma.rn.f32x2 %0, %1, %2, %0;" : "+l"(c) : "l"(a), "l"(b))

__device__ __forceinline__ float lo_f(unsigned long long u) {
    return __uint_as_float((unsigned)u);
}
__device__ __forceinline__ float hi_f(unsigned long long u) {
    return __uint_as_float((unsigned)(u >> 32));
}

// Scratch: partial logits [2][T_TOK][NEXP] (4 MB)
__device__ float g_part[2][T_TOK][NEXP];

// ----------------------------------------------------------------------------
// Kernel 1: split-K=2 fp32 GEMM. blockIdx.y = K-half. Each logit half is ONE
// serial ascending fmaf chain (packed f32x2 lanes are independent tokens).
// Block: 64 tokens x 64 experts, 256 threads, 4 tok x 4 exp per thread.
// W is stored DUPLICATED in smem (each value twice) so packed b-operands come
// straight from LDS.128 broadcast loads — no register MOV duplication.
// Smem = 24 KB -> 2 CTAs/SM (16 warps) to hide LDS->FMA latency.
// ----------------------------------------------------------------------------
__global__ __launch_bounds__(NTH)
void router_gemm(const float* __restrict__ x, const float* __restrict__ w)
{
    __shared__ __align__(16) float Xs[2][BK][BM];     // [buf][k][token]    8 KB
    __shared__ __align__(16) float Ws2[2][BK][WDUP];  // [buf][k][dup exp] 16 KB

    const int tid = threadIdx.x;
    const int t0  = blockIdx.x * BM;
    const int k0  = blockIdx.y * KHALF;

    const int tt = tid & 15;         // token quad  -> tokens tt*4 .. tt*4+3
    const int te = tid >> 4;         // expert quad -> experts te*4 .. te*4+3

    unsigned long long acc[2][4] = {};   // [token pair][expert]

    // staging assignments (one float4 each for X and W per thread)
    const int xrow = tid >> 2;            // token row (0..63)
    const int xck  = (tid & 3) * 4;       // k offset within BK (0,4,8,12)
    const int wrow = tid >> 4;            // k row (0..15)
    const int wck  = (tid & 15) * 4;      // expert col (0,4,..,60)

    const float* xg = x + (size_t)(t0 + xrow) * DDIM + k0 + xck;
    const float* wg = w + (size_t)(k0 + wrow) * NEXP + wck;

    // ---- prime: tile 0 -> buf 0 ----
    {
        float4 A = *(const float4*)xg;
        float4 W = *(const float4*)wg;
        Xs[0][xck + 0][xrow] = A.x;
        Xs[0][xck + 1][xrow] = A.y;
        Xs[0][xck + 2][xrow] = A.z;
        Xs[0][xck + 3][xrow] = A.w;
        float* d = &Ws2[0][wrow][wck * 2];
        *(float4*)(d + 0) = make_float4(W.x, W.x, W.y, W.y);
        *(float4*)(d + 4) = make_float4(W.z, W.z, W.w, W.w);
    }
    __syncthreads();

    for (int it = 0; it < NITER; ++it) {
        const int buf = it & 1;
        const bool pf = (it + 1 < NITER);

        float4 A, W;
        if (pf) {
            A = *(const float4*)(xg + (it + 1) * BK);
            W = *(const float4*)(wg + (size_t)(it + 1) * BK * NEXP);
        }

        const float* xsb = &Xs[buf][0][tt * 4];
        const float* wsb = &Ws2[buf][0][te * 8];

#pragma unroll
        for (int kk = 0; kk < BK; ++kk) {
            ulonglong2 a  = *(const ulonglong2*)(xsb + kk * BM);      // 2 token pairs
            ulonglong2 b0 = *(const ulonglong2*)(wsb + kk * WDUP);     // dup exp 0,1
            ulonglong2 b1 = *(const ulonglong2*)(wsb + kk * WDUP + 4); // dup exp 2,3
            FMA2(acc[0][0], a.x, b0.x); FMA2(acc[0][1], a.x, b0.y);
            FMA2(acc[0][2], a.x, b1.x); FMA2(acc[0][3], a.x, b1.y);
            FMA2(acc[1][0], a.y, b0.x); FMA2(acc[1][1], a.y, b0.y);
            FMA2(acc[1][2], a.y, b1.x); FMA2(acc[1][3], a.y, b1.y);
        }

        if (pf) {
            const int nb = buf ^ 1;
            Xs[nb][xck + 0][xrow] = A.x;
            Xs[nb][xck + 1][xrow] = A.y;
            Xs[nb][xck + 2][xrow] = A.z;
            Xs[nb][xck + 3][xrow] = A.w;
            float* d = &Ws2[nb][wrow][wck * 2];
            *(float4*)(d + 0) = make_float4(W.x, W.x, W.y, W.y);
            *(float4*)(d + 4) = make_float4(W.z, W.z, W.w, W.w);
        }
        __syncthreads();
    }

    // write partials for this K-half
    float* op = &g_part[blockIdx.y][t0][0];
#pragma unroll
    for (int p = 0; p < 2; ++p) {
        const int r0 = tt * 4 + 2 * p;
        *(float4*)(op + (size_t)r0 * NEXP + te * 4) =
            make_float4(lo_f(acc[p][0]), lo_f(acc[p][1]),
                        lo_f(acc[p][2]), lo_f(acc[p][3]));
        *(float4*)(op + (size_t)(r0 + 1) * NEXP + te * 4) =
            make_float4(hi_f(acc[p][0]), hi_f(acc[p][1]),
                        hi_f(acc[p][2]), hi_f(acc[p][3]));
    }
}

// ----------------------------------------------------------------------------
// Kernel 2: one warp per token. logit = half0 + half1 (ascending slice order,
// scalar rn add -> identical rounding to the R4 passing kernel), then top-8
// (tie: lowest index, matching jax.lax.top_k) + softmax.
// ----------------------------------------------------------------------------
__global__ __launch_bounds__(256)
void router_topk(float* __restrict__ out, int half)
{
    const int warp = (int)((blockIdx.x * blockDim.x + threadIdx.x) >> 5);
    const int lane = threadIdx.x & 31;
    if (warp >= T_TOK) return;

    float v0 = g_part[0][warp][lane]      + g_part[1][warp][lane];
    float v1 = g_part[0][warp][lane + 32] + g_part[1][warp][lane + 32];

    float topv[TOPK];
    int   topi[TOPK];
#pragma unroll
    for (int j = 0; j < TOPK; j++) {
        float bv; int bi;
        if (v0 >= v1) { bv = v0; bi = lane; }
        else          { bv = v1; bi = lane + 32; }
#pragma unroll
        for (int off = 16; off; off >>= 1) {
            float ov = __shfl_xor_sync(0xffffffffu, bv, off);
            int   oi = __shfl_xor_sync(0xffffffffu, bi, off);
            if (ov > bv || (ov == bv && oi < bi)) { bv = ov; bi = oi; }
        }
        topv[j] = bv;
        topi[j] = bi;
        if (bi == lane)           v0 = -INFINITY;
        else if (bi == lane + 32) v1 = -INFINITY;
    }

    const float mx = topv[0];
    float e[TOPK];
    float sum = 0.0f;
#pragma unroll
    for (int j = 0; j < TOPK; j++) { e[j] = expf(topv[j] - mx); sum += e[j]; }
    const float inv = 1.0f / sum;

    if (lane < TOPK) {
        const size_t g = (size_t)warp * TOPK + lane;
        out[g]        = e[lane] * inv;
        out[half + g] = (float)topi[lane];
    }
}

// ----------------------------------------------------------------------------
extern "C" void kernel_launch(void* const* d_in, const int* in_sizes, int n_in,
                              void* d_out, int out_size)
{
    const float* x = (const float*)d_in[0];
    const float* w = (const float*)d_in[1];
    float* out = (float*)d_out;
    const int half = out_size >> 1;

    dim3 grid1(T_TOK / BM, 2);
    router_gemm<<<grid1, NTH>>>(x, w);

    router_topk<<<T_TOK / 8, 256>>>(out, half);
}